// round 7
// baseline (speedup 1.0000x reference)
#include <cuda_runtime.h>
#include <cuda_bf16.h>

constexpr int TIMESTEPS = 1000;
constexpr int B = 4;
constexpr int N = 2048;                                // power of two
constexpr long long E = (long long)N * (N - 1) / 2;    // 2,096,128
constexpr int EI = (int)E;
constexpr int NBLK = B * (N / 2);                      // 4096 blocks
constexpr int NTHR = 256;

// Cross-block reduction scratch. g_count self-resets (atomicInc wrap) -> graph-replay safe.
__device__ float        g_partials[NBLK];
__device__ unsigned int g_count = 0;

struct Consts { float flip_t, omt, qt00, qt01, qt10, qt11; };

__device__ __forceinline__ float ex2(float x) {
    float r; asm("ex2.approx.f32 %0, %1;" : "=f"(r) : "f"(x)); return r;
}
__device__ __forceinline__ float rcp(float x) {
    float r; asm("rcp.approx.f32 %0, %1;" : "=f"(r) : "f"(x)); return r;
}

// Per-element loss term: qt via 4-entry LUT on (a!=0, x1); MUFU softplus.
__device__ __forceinline__ float term(int a, float uu, float x, const Consts& c) {
    bool  ab = (a != 0);
    float pa = ab ? c.omt : c.flip_t;          // Qt[t][a, 1]
    bool  x1 = uu < pa;                        // sampled bit
    float q0 = ab ? c.qt10 : c.qt00;
    float q1 = ab ? c.qt11 : c.qt01;
    float qt = x1 ? q1 : q0;
    float sp = __logf(1.0f + __expf(-fabsf(x)));   // log1p(exp(-|x|))
    return fmaf(-x, qt, fmaxf(x, 0.0f) + sp);
}

__device__ __forceinline__ float term4(int4 A, float4 U, float4 X, const Consts& c) {
    return term(A.x, U.x, X.x, c) + term(A.y, U.y, X.y, c)
         + term(A.z, U.z, X.z, c) + term(A.w, U.w, X.w, c);
}

// One CTA per (b, k): rows i=k and i=N-1-k -> exactly 2047 elements.
// All three vector-load groups (half-A slot, half-B slot1, half-B slot2) are
// issued UNCONDITIONALLY with clamped-to-valid addresses so ptxas can keep
// ~9 load groups in flight per warp; only the accumulation is predicated.
// __launch_bounds__(256,4) lifts the register cap to ~64 so the batched
// payloads actually fit in registers instead of being serialized.
__global__ __launch_bounds__(NTHR, 4)
void loss_kernel(const int* __restrict__ adj, const int* __restrict__ t,
                 const float* __restrict__ u, const float* __restrict__ q,
                 float* __restrict__ out) {
    __shared__ float warp_sums[8];
    __shared__ bool  is_last;

    const int tid  = threadIdx.x;
    const int bidx = blockIdx.x;
    const int b    = bidx >> 10;        // / (N/2)
    const int k    = bidx & 1023;       // % (N/2)

    // Per-thread fp32 constants (MUFU) — no FP64, no barrier.
    Consts c;
    {
        const float L2_098 = -0.0291463173f;               // log2(0.98)
        int   tb = t[b];
        float pt = ex2((float)(tb + 1) * L2_098);          // 0.98^(t+1)
        int   tm1 = (tb + TIMESTEPS - 1) % TIMESTEPS;      // Qt[t-1] wraps at t=0
        float pp = ex2((float)(tm1 + 1) * L2_098);
        c.flip_t = 0.5f - 0.5f * pt;
        c.omt    = 0.5f + 0.5f * pt;
        float flip_p = 0.5f - 0.5f * pp;
        float omp    = 0.5f + 0.5f * pp;
        float r_omt  = rcp(c.omt);
        float r_flip = rcp(c.flip_t);
        // qt[ab][x1] = Qt0[x1,1] * Qt[t-1][ab,1] / Qt[t][ab,x1]
        c.qt00 = 0.01f * flip_p * r_omt;
        c.qt01 = 0.99f * flip_p * r_flip;
        c.qt10 = 0.01f * omp    * r_flip;
        c.qt11 = 0.99f * omp    * r_omt;
    }

    const int iA = k;            // len iA in [0,1023],   nvA <= 255
    const int iB = N - 1 - k;    // len iB in [1024,2047], nvB in [256,511]
    const int nvA = iA >> 2, remA = iA & 3;
    const int nvB = iB >> 2, remB = iB & 3;

    const int rowbaseA = ((b << 11) + iA) << 11;
    const int rowbaseB = ((b << 11) + iB) << 11;
    const int qbase    = b * EI;
    const int qrowA    = qbase + ((iA * (iA - 1)) >> 1);
    const int qrowB    = qbase + ((iB * (iB - 1)) >> 1);

    const bool pA  = tid < nvA;
    const bool pB2 = (tid + NTHR) < nvB;

    // Clamped vector indices (slot 0 of each row is always readable: iB>=1024
    // guarantees >=256 vectors in row B; row A index clamps to vector 0 which
    // lies inside the allocated row even when iA==0).
    const int vA  = pA  ? tid        : 0;
    const int vB2 = pB2 ? tid + NTHR : 0;

    // ---- issue ALL main loads up front ----
    int4   Aa  = reinterpret_cast<const int4*>(adj + rowbaseA)[vA];
    float4 Ua  = reinterpret_cast<const float4*>(u + rowbaseA)[vA];
    const float* qa = q + qrowA + (vA << 2);
    float4 Xa  = make_float4(qa[0], qa[1], qa[2], qa[3]);

    int4   Ab1 = reinterpret_cast<const int4*>(adj + rowbaseB)[tid];
    float4 Ub1 = reinterpret_cast<const float4*>(u + rowbaseB)[tid];
    const float* qb1 = q + qrowB + (tid << 2);
    float4 Xb1 = make_float4(qb1[0], qb1[1], qb1[2], qb1[3]);

    int4   Ab2 = reinterpret_cast<const int4*>(adj + rowbaseB)[vB2];
    float4 Ub2 = reinterpret_cast<const float4*>(u + rowbaseB)[vB2];
    const float* qb2 = q + qrowB + (vB2 << 2);
    float4 Xb2 = make_float4(qb2[0], qb2[1], qb2[2], qb2[3]);

    // ---- compute (accumulation predicated, loads already in flight) ----
    float s = 0.0f;
    s += pA  ? term4(Aa,  Ua,  Xa,  c) : 0.0f;
    s +=       term4(Ab1, Ub1, Xb1, c);
    s += pB2 ? term4(Ab2, Ub2, Xb2, c) : 0.0f;

    // ---- tails (<=3 threads each) ----
    if (tid < remA) {
        int j = (nvA << 2) + tid;
        s += term(adj[rowbaseA + j], u[rowbaseA + j], q[qrowA + j], c);
    }
    if (tid < remB) {
        int j = (nvB << 2) + tid;
        s += term(adj[rowbaseB + j], u[rowbaseB + j], q[qrowB + j], c);
    }

    // Block reduction
    #pragma unroll
    for (int off = 16; off; off >>= 1) s += __shfl_down_sync(0xffffffffu, s, off);
    const int lane = tid & 31, wid = tid >> 5;
    if (lane == 0) warp_sums[wid] = s;
    __syncthreads();
    if (wid == 0) {
        s = (lane < 8) ? warp_sums[lane] : 0.0f;
        #pragma unroll
        for (int off = 4; off; off >>= 1) s += __shfl_down_sync(0xffffffffu, s, off);
        if (lane == 0) g_partials[bidx] = s;
    }

    // Last-block-standing final reduction (counter wraps to 0 -> replayable)
    __threadfence();
    if (tid == 0) {
        unsigned v = atomicInc(&g_count, NBLK - 1);
        is_last = (v == NBLK - 1);
    }
    __syncthreads();
    if (is_last) {
        float acc = 0.0f;
        for (int idx = tid; idx < NBLK; idx += NTHR) acc += g_partials[idx];
        #pragma unroll
        for (int off = 16; off; off >>= 1) acc += __shfl_down_sync(0xffffffffu, acc, off);
        if (lane == 0) warp_sums[wid] = acc;
        __syncthreads();
        if (wid == 0) {
            acc = (lane < 8) ? warp_sums[lane] : 0.0f;
            #pragma unroll
            for (int off = 4; off; off >>= 1) acc += __shfl_down_sync(0xffffffffu, acc, off);
            if (lane == 0) out[0] = acc * (1.0f / (float)(B * E));
        }
    }
}

extern "C" void kernel_launch(void* const* d_in, const int* in_sizes, int n_in,
                              void* d_out, int out_size) {
    // metadata order: adj_start (int32), t (int32), u (f32), q_approx (f32)
    const int*   adj = (const int*)d_in[0];
    const int*   t   = (const int*)d_in[1];
    const float* u   = (const float*)d_in[2];
    const float* q   = (const float*)d_in[3];
    float* out = (float*)d_out;

    loss_kernel<<<NBLK, NTHR>>>(adj, t, u, q, out);
}

// round 10
// speedup vs baseline: 1.3367x; 1.3367x over previous
#include <cuda_runtime.h>
#include <cuda_bf16.h>
#include <cstdint>

constexpr int TIMESTEPS = 1000;
constexpr int B = 4;
constexpr int N = 2048;                                // power of two
constexpr long long E = (long long)N * (N - 1) / 2;    // 2,096,128
constexpr int EI = (int)E;
constexpr int QTOT = B * EI;                           // total q elements
constexpr int NBLK = B * (N / 2);                      // 4096 blocks
constexpr int NTHR = 256;

// Cross-block reduction scratch. g_count self-resets (atomicInc wrap) -> graph-replay safe.
__device__ float        g_partials[NBLK];
__device__ unsigned int g_count = 0;

struct Consts { float flip_t, omt, qt00, qt01, qt10, qt11; };

__device__ __forceinline__ float ex2(float x) {
    float r; asm("ex2.approx.f32 %0, %1;" : "=f"(r) : "f"(x)); return r;
}
__device__ __forceinline__ float rcp(float x) {
    float r; asm("rcp.approx.f32 %0, %1;" : "=f"(r) : "f"(x)); return r;
}
// 16B global->shared async copy, L1-bypass (cg).
__device__ __forceinline__ void cpa16(uint32_t dst, const void* src) {
    asm volatile("cp.async.cg.shared.global [%0], [%1], 16;" :: "r"(dst), "l"(src));
}
// 4B global->shared async copy (for buffer-end tail chunks only).
__device__ __forceinline__ void cpa4(uint32_t dst, const void* src) {
    asm volatile("cp.async.ca.shared.global [%0], [%1], 4;" :: "r"(dst), "l"(src));
}
// Stage one 4-element q chunk; guards against reading past the end of q.
__device__ __forceinline__ void stage_q(uint32_t sq, int slot, const float* q, int gbase) {
    if (gbase + 4 <= QTOT) {
        cpa16(sq + slot * 16, q + gbase);
    } else {
        #pragma unroll
        for (int e = 0; e < 4; ++e)
            if (gbase + e < QTOT) cpa4(sq + slot * 16 + e * 4, q + gbase + e);
    }
}

// Per-element loss term: qt via 4-entry LUT on (a!=0, x1); MUFU softplus.
__device__ __forceinline__ float term(int a, float uu, float x, const Consts& c) {
    bool  ab = (a != 0);
    float pa = ab ? c.omt : c.flip_t;          // Qt[t][a, 1]
    bool  x1 = uu < pa;                        // sampled bit
    float q0 = ab ? c.qt10 : c.qt00;
    float q1 = ab ? c.qt11 : c.qt01;
    float qt = x1 ? q1 : q0;
    float sp = __logf(1.0f + __expf(-fabsf(x)));   // log1p(exp(-|x|))
    return fmaf(-x, qt, fmaxf(x, 0.0f) + sp);
}

// One CTA per (b,k): rows i=k (len iA<=1023) and i=N-1-k (len iB in [1024,2047]),
// iA+iB = 2047 exactly. The whole 24.7KB workload is staged into SMEM with
// cp.async (no register payload -> MLP without occupancy loss), then computed
// from SMEM with coalesced stride-256 LDS.
__global__ __launch_bounds__(NTHR)
void loss_kernel(const int* __restrict__ adj, const int* __restrict__ t,
                 const float* __restrict__ u, const float* __restrict__ q,
                 float* __restrict__ out) {
    __shared__ int   s_adj[2056];     // packed: row A chunks, then row B chunks
    __shared__ float s_u[2056];
    __shared__ float s_q[2064];       // rounded-out to 16B on both rows
    __shared__ float warp_sums[8];
    __shared__ bool  is_last;

    const int tid  = threadIdx.x;
    const int bidx = blockIdx.x;
    const int b    = bidx >> 10;        // / (N/2)
    const int k    = bidx & 1023;       // % (N/2)

    const int iA = k;
    const int iB = N - 1 - k;
    const int rowbaseA = ((b << 11) + iA) << 11;     // (b*N+iA)*N
    const int rowbaseB = ((b << 11) + iB) << 11;
    const int qrowA = b * EI + ((iA * (iA - 1)) >> 1);
    const int qrowB = b * EI + ((iB * (iB - 1)) >> 1);

    // Chunk geometry (16B = 4 elements per chunk). adj/u chunks never cross the
    // row end (iX+pad <= N); q chunks can cross the BUFFER end only in the very
    // last row -> stage_q guards that case.
    const int cA   = (iA + 3) >> 2;                  // <= 256
    const int cB   = (iB + 3) >> 2;                  // <= 512
    const int cA4  = cA << 2;                        // row B element base in s_adj/s_u
    const int galA = qrowA & ~3, ofsA = qrowA & 3;   // q row A aligned start
    const int galB = qrowB & ~3, ofsB = qrowB & 3;
    const int cqA  = (iA + ofsA + 3) >> 2;           // <= 257
    const int cqB  = (iB + ofsB + 3) >> 2;           // <= 513
    const int cqA4 = cqA << 2;

    const uint32_t sa = (uint32_t)__cvta_generic_to_shared(s_adj);
    const uint32_t su = (uint32_t)__cvta_generic_to_shared(s_u);
    const uint32_t sq = (uint32_t)__cvta_generic_to_shared(s_q);

    // ---- stage everything with cp.async ----
    if (tid < cA)        cpa16(sa + tid * 16,              adj + rowbaseA + (tid << 2));
    if (tid < cB)        cpa16(sa + (cA + tid) * 16,       adj + rowbaseB + (tid << 2));
    if (tid + 256 < cB)  cpa16(sa + (cA + tid + 256) * 16, adj + rowbaseB + ((tid + 256) << 2));

    if (tid < cA)        cpa16(su + tid * 16,              u + rowbaseA + (tid << 2));
    if (tid < cB)        cpa16(su + (cA + tid) * 16,       u + rowbaseB + (tid << 2));
    if (tid + 256 < cB)  cpa16(su + (cA + tid + 256) * 16, u + rowbaseB + ((tid + 256) << 2));

    if (tid < cqA)       stage_q(sq, tid,              q, galA + (tid << 2));
    if (tid + 256 < cqA) stage_q(sq, tid + 256,        q, galA + ((tid + 256) << 2));

    if (tid < cqB)       stage_q(sq, cqA + tid,        q, galB + (tid << 2));
    if (tid + 256 < cqB) stage_q(sq, cqA + tid + 256,  q, galB + ((tid + 256) << 2));
    if (tid + 512 < cqB) stage_q(sq, cqA + tid + 512,  q, galB + ((tid + 512) << 2));

    asm volatile("cp.async.commit_group;" ::: "memory");

    // Per-thread fp32 constants (MUFU) — computed while copies are in flight.
    Consts c;
    {
        const float L2_098 = -0.0291463173f;               // log2(0.98)
        int   tb = t[b];
        float pt = ex2((float)(tb + 1) * L2_098);          // 0.98^(t+1)
        int   tm1 = (tb + TIMESTEPS - 1) % TIMESTEPS;      // Qt[t-1] wraps at t=0
        float pp = ex2((float)(tm1 + 1) * L2_098);
        c.flip_t = 0.5f - 0.5f * pt;
        c.omt    = 0.5f + 0.5f * pt;
        float flip_p = 0.5f - 0.5f * pp;
        float omp    = 0.5f + 0.5f * pp;
        float r_omt  = rcp(c.omt);
        float r_flip = rcp(c.flip_t);
        // qt[ab][x1] = Qt0[x1,1] * Qt[t-1][ab,1] / Qt[t][ab,x1]
        c.qt00 = 0.01f * flip_p * r_omt;
        c.qt01 = 0.99f * flip_p * r_flip;
        c.qt10 = 0.01f * omp    * r_flip;
        c.qt11 = 0.99f * omp    * r_omt;
    }

    asm volatile("cp.async.wait_group 0;" ::: "memory");
    __syncthreads();

    // ---- compute from SMEM: 8 stride-256 slots (2048 slots, 1 dummy) ----
    float s = 0.0f;
    #pragma unroll
    for (int it = 0; it < 8; ++it) {
        int e = tid + (it << 8);
        if (e < N - 1) {
            bool inA = e < iA;
            int  j   = inA ? e : e - iA;
            int  ai  = inA ? j : cA4 + j;
            int  qi  = inA ? (ofsA + j) : (cqA4 + ofsB + j);
            s += term(s_adj[ai], s_u[ai], s_q[qi], c);
        }
    }

    // Block reduction
    #pragma unroll
    for (int off = 16; off; off >>= 1) s += __shfl_down_sync(0xffffffffu, s, off);
    const int lane = tid & 31, wid = tid >> 5;
    if (lane == 0) warp_sums[wid] = s;
    __syncthreads();
    if (wid == 0) {
        s = (lane < 8) ? warp_sums[lane] : 0.0f;
        #pragma unroll
        for (int off = 4; off; off >>= 1) s += __shfl_down_sync(0xffffffffu, s, off);
        if (lane == 0) g_partials[bidx] = s;
    }

    // Last-block-standing final reduction (counter wraps to 0 -> replayable)
    __threadfence();
    if (tid == 0) {
        unsigned v = atomicInc(&g_count, NBLK - 1);
        is_last = (v == NBLK - 1);
    }
    __syncthreads();
    if (is_last) {
        float acc = 0.0f;
        for (int idx = tid; idx < NBLK; idx += NTHR) acc += g_partials[idx];
        #pragma unroll
        for (int off = 16; off; off >>= 1) acc += __shfl_down_sync(0xffffffffu, acc, off);
        if (lane == 0) warp_sums[wid] = acc;
        __syncthreads();
        if (wid == 0) {
            acc = (lane < 8) ? warp_sums[lane] : 0.0f;
            #pragma unroll
            for (int off = 4; off; off >>= 1) acc += __shfl_down_sync(0xffffffffu, acc, off);
            if (lane == 0) out[0] = acc * (1.0f / (float)(B * E));
        }
    }
}

extern "C" void kernel_launch(void* const* d_in, const int* in_sizes, int n_in,
                              void* d_out, int out_size) {
    // metadata order: adj_start (int32), t (int32), u (f32), q_approx (f32)
    const int*   adj = (const int*)d_in[0];
    const int*   t   = (const int*)d_in[1];
    const float* u   = (const float*)d_in[2];
    const float* q   = (const float*)d_in[3];
    float* out = (float*)d_out;

    // Context-level (not stream) call: capture-legal, deterministic, no alloc.
    // Maximizes the SMEM carveout so 8 CTAs x 24.7KB fit per SM.
    cudaFuncSetAttribute(loss_kernel,
                         cudaFuncAttributePreferredSharedMemoryCarveout,
                         cudaSharedmemCarveoutMaxShared);

    loss_kernel<<<NBLK, NTHR>>>(adj, t, u, q, out);
}

// round 11
// speedup vs baseline: 1.3384x; 1.0013x over previous
#include <cuda_runtime.h>
#include <cuda_bf16.h>
#include <cstdint>

constexpr int TIMESTEPS = 1000;
constexpr int B = 4;
constexpr int N = 2048;                                // power of two
constexpr long long E = (long long)N * (N - 1) / 2;    // 2,096,128
constexpr int EI = (int)E;
constexpr int QTOT = B * EI;                           // total q elements (fits int)
constexpr int NBLK = B * (N / 2);                      // 4096 blocks
constexpr int NTHR = 256;

// Cross-block reduction scratch. g_count self-resets (atomicInc wrap) -> graph-replay safe.
__device__ float        g_partials[NBLK];
__device__ unsigned int g_count = 0;

struct Consts { float flip_t, omt, qt00, qt01, qt10, qt11; };

__device__ __forceinline__ float ex2(float x) {
    float r; asm("ex2.approx.f32 %0, %1;" : "=f"(r) : "f"(x)); return r;
}
__device__ __forceinline__ float rcp(float x) {
    float r; asm("rcp.approx.f32 %0, %1;" : "=f"(r) : "f"(x)); return r;
}
// 16B global->shared async copy, L1-bypass (cg).
__device__ __forceinline__ void cpa16(uint32_t dst, const void* src) {
    asm volatile("cp.async.cg.shared.global [%0], [%1], 16;" :: "r"(dst), "l"(src));
}

// Per-element loss term: qt via 4-entry LUT on (a!=0, x1); MUFU softplus.
__device__ __forceinline__ float term(int a, float uu, float x, const Consts& c) {
    bool  ab = (a != 0);
    float pa = ab ? c.omt : c.flip_t;          // Qt[t][a, 1]
    bool  x1 = uu < pa;                        // sampled bit
    float q0 = ab ? c.qt10 : c.qt00;
    float q1 = ab ? c.qt11 : c.qt01;
    float qt = x1 ? q1 : q0;
    float sp = __logf(1.0f + __expf(-fabsf(x)));   // log1p(exp(-|x|))
    return fmaf(-x, qt, fmaxf(x, 0.0f) + sp);
}

// One CTA per (b,k): rows i=k (iA<=1023) and i=N-1-k (iB in [1024,2047]).
// Two cp.async groups: group0 = row-B streams (70% of work), group1 = row-A.
// Compute of row B overlaps the in-flight row-A copies.
__global__ __launch_bounds__(NTHR)
void loss_kernel(const int* __restrict__ adj, const int* __restrict__ t,
                 const float* __restrict__ u, const float* __restrict__ q,
                 float* __restrict__ out) {
    __shared__ int   s_adj[2056];     // packed: rowA chunks then rowB chunks
    __shared__ float s_u[2056];
    __shared__ float s_q[2064];       // 16B-rounded on both rows
    __shared__ float warp_sums[8];
    __shared__ bool  is_last;

    const int tid = threadIdx.x;
    const int wb  = tid & ~31;          // warp base (uniform predicates)
    const int bidx = blockIdx.x;
    const int b    = bidx >> 10;        // / (N/2)
    const int k    = bidx & 1023;       // % (N/2)

    const int iA = k;
    const int iB = N - 1 - k;
    const int rowbaseA = ((b << 11) + iA) << 11;     // (b*N+iA)*N
    const int rowbaseB = ((b << 11) + iB) << 11;
    const int qrowA = b * EI + ((iA * (iA - 1)) >> 1);
    const int qrowB = b * EI + ((iB * (iB - 1)) >> 1);

    // Chunk geometry (16B = 4 elements per chunk). adj/u chunks stay inside the
    // 2048-element row; q chunks are address-clamped at the buffer end.
    const int cA   = (iA + 3) >> 2;                  // <= 256
    const int cB   = (iB + 3) >> 2;                  // in [256, 512]
    const int cA4  = cA << 2;
    const int galA = qrowA & ~3, ofsA = qrowA & 3;
    const int galB = qrowB & ~3, ofsB = qrowB & 3;
    const int cqA  = (iA + ofsA + 3) >> 2;           // <= 257
    const int cqB  = (iB + ofsB + 3) >> 2;           // in [256, 513]
    const int cqA4 = cqA << 2;

    const uint32_t sa = (uint32_t)__cvta_generic_to_shared(s_adj);
    const uint32_t su = (uint32_t)__cvta_generic_to_shared(s_u);
    const uint32_t sq = (uint32_t)__cvta_generic_to_shared(s_q);
    const uint32_t saB = sa + cA4 * 4,  suB = su + cA4 * 4,  sqB = sq + cqA4 * 4;

    const char* gaB = (const char*)(adj + rowbaseB);
    const char* guB = (const char*)(u   + rowbaseB);
    const char* gaA = (const char*)(adj + rowbaseA);
    const char* guA = (const char*)(u   + rowbaseA);

    // ---- group 0: row B streams (big row first) ----
    cpa16(saB + tid * 16, gaB + tid * 16);                       // cB >= 256: unconditional
    cpa16(suB + tid * 16, guB + tid * 16);
    cpa16(sqB + tid * 16, q + (galB + (tid << 2)));              // cqB >= 256, in-bounds
    if (256 + wb < cB) {                                         // warp-uniform
        int cc = min(tid + 256, cB - 1);                         // dup-clamp: benign
        cpa16(saB + cc * 16, gaB + cc * 16);
        cpa16(suB + cc * 16, guB + cc * 16);
    }
    if (256 + wb < cqB) {
        int cc = min(tid + 256, cqB - 1);
        int gb = min(galB + (cc << 2), QTOT - 4);                // buffer-end clamp
        cpa16(sqB + cc * 16, q + gb);
    }
    if (tid == 0 && cqB > 512) {                                 // rare 513th chunk
        int gb = min(galB + 2048, QTOT - 4);
        cpa16(sqB + 512 * 16, q + gb);
    }
    asm volatile("cp.async.commit_group;" ::: "memory");

    // ---- group 1: row A streams ----
    if (wb < cA) {
        int cc = min(tid, cA - 1);
        cpa16(sa + cc * 16, gaA + cc * 16);
        cpa16(su + cc * 16, guA + cc * 16);
    }
    if (wb < cqA) {
        int cc = min(tid, cqA - 1);
        int gb = min(galA + (cc << 2), QTOT - 4);
        cpa16(sq + cc * 16, q + gb);
    }
    if (tid == 0 && cqA > 256) {
        int gb = min(galA + 1024, QTOT - 4);
        cpa16(sq + 256 * 16, q + gb);
    }
    asm volatile("cp.async.commit_group;" ::: "memory");

    // Per-thread fp32 constants (MUFU) — computed while copies are in flight.
    Consts c;
    {
        const float L2_098 = -0.0291463173f;               // log2(0.98)
        int   tb = t[b];
        float pt = ex2((float)(tb + 1) * L2_098);          // 0.98^(t+1)
        int   tm1 = (tb + TIMESTEPS - 1) % TIMESTEPS;      // Qt[t-1] wraps at t=0
        float pp = ex2((float)(tm1 + 1) * L2_098);
        c.flip_t = 0.5f - 0.5f * pt;
        c.omt    = 0.5f + 0.5f * pt;
        float flip_p = 0.5f - 0.5f * pp;
        float omp    = 0.5f + 0.5f * pp;
        float r_omt  = rcp(c.omt);
        float r_flip = rcp(c.flip_t);
        // qt[ab][x1] = Qt0[x1,1] * Qt[t-1][ab,1] / Qt[t][ab,x1]
        c.qt00 = 0.01f * flip_p * r_omt;
        c.qt01 = 0.99f * flip_p * r_flip;
        c.qt10 = 0.01f * omp    * r_flip;
        c.qt11 = 0.99f * omp    * r_omt;
    }

    // ---- wait for row B only; row A still streaming ----
    asm volatile("cp.async.wait_group 1;" ::: "memory");
    __syncthreads();

    const int*   aB = s_adj + cA4;
    const float* uB = s_u   + cA4;
    const float* qB = s_q   + cqA4 + ofsB;

    float s = 0.0f;
    #pragma unroll
    for (int it = 0; it < 4; ++it) {                 // e < 1024 <= iB: unconditional
        int e = tid + (it << 8);
        s += term(aB[e], uB[e], qB[e], c);
    }
    #pragma unroll
    for (int it = 4; it < 8; ++it) {
        int e = tid + (it << 8);
        if (e < iB) s += term(aB[e], uB[e], qB[e], c);
    }

    // ---- row A ----
    asm volatile("cp.async.wait_group 0;" ::: "memory");
    __syncthreads();

    const float* qA = s_q + ofsA;
    #pragma unroll
    for (int it = 0; it < 4; ++it) {
        int e = tid + (it << 8);
        if (e < iA) s += term(s_adj[e], s_u[e], qA[e], c);
    }

    // Block reduction
    #pragma unroll
    for (int off = 16; off; off >>= 1) s += __shfl_down_sync(0xffffffffu, s, off);
    const int lane = tid & 31, wid = tid >> 5;
    if (lane == 0) warp_sums[wid] = s;
    __syncthreads();
    if (wid == 0) {
        s = (lane < 8) ? warp_sums[lane] : 0.0f;
        #pragma unroll
        for (int off = 4; off; off >>= 1) s += __shfl_down_sync(0xffffffffu, s, off);
        if (lane == 0) g_partials[bidx] = s;
    }

    // Last-block-standing final reduction (counter wraps to 0 -> replayable)
    __threadfence();
    if (tid == 0) {
        unsigned v = atomicInc(&g_count, NBLK - 1);
        is_last = (v == NBLK - 1);
    }
    __syncthreads();
    if (is_last) {
        float acc = 0.0f;
        for (int idx = tid; idx < NBLK; idx += NTHR) acc += g_partials[idx];
        #pragma unroll
        for (int off = 16; off; off >>= 1) acc += __shfl_down_sync(0xffffffffu, acc, off);
        if (lane == 0) warp_sums[wid] = acc;
        __syncthreads();
        if (wid == 0) {
            acc = (lane < 8) ? warp_sums[lane] : 0.0f;
            #pragma unroll
            for (int off = 4; off; off >>= 1) acc += __shfl_down_sync(0xffffffffu, acc, off);
            if (lane == 0) out[0] = acc * (1.0f / (float)(B * E));
        }
    }
}

extern "C" void kernel_launch(void* const* d_in, const int* in_sizes, int n_in,
                              void* d_out, int out_size) {
    // metadata order: adj_start (int32), t (int32), u (f32), q_approx (f32)
    const int*   adj = (const int*)d_in[0];
    const int*   t   = (const int*)d_in[1];
    const float* u   = (const float*)d_in[2];
    const float* q   = (const float*)d_in[3];
    float* out = (float*)d_out;

    // Context-level (not stream) call: capture-legal, deterministic, no alloc.
    cudaFuncSetAttribute(loss_kernel,
                         cudaFuncAttributePreferredSharedMemoryCarveout,
                         cudaSharedmemCarveoutMaxShared);

    loss_kernel<<<NBLK, NTHR>>>(adj, t, u, q, out);
}